// round 9
// baseline (speedup 1.0000x reference)
#include <cuda_runtime.h>
#include <cuda_fp16.h>

// Bilinear flow warp: fp16 overlapped-pair SMEM tile, register-pipelined fill,
// register-dieted to avoid spills under the 64-reg/2-block cap.
//   img: [B=8, C=16, H=512, W=512] f32
//   flo: [B=8, 2,   H=512, W=512] f32
//   out: [B=8, C=16, H=512, W=512] f32
//
// Block = one (b, 8-row) full-width strip, 512 threads (one column each).
// Tile: 16 rows of __half2 pairs tile[r][x] = (v[x], v[x+1]), row stride 516.
// One aligned LDS.32 per gather row fetches both x-neighbors. Channel c+1 is
// LDG'd into 4 float4 registers before channel c's gather phase and STS'd
// after it. Weights fp32-exact (u16.16). Out-of-halo pixels (P~1e-4) use
// exact fp32 global loads.

#define B_    8
#define C_    16
#define H_    512
#define W_    512
#define HW_   (H_ * W_)
#define TY    8
#define HALO  4
#define TROWS (TY + 2 * HALO)      // 16
#define STRIDE 516                 // half2 units per tile row
#define THREADS 512
#define FB_BIT  (1 << 22)

__global__ __launch_bounds__(THREADS, 2) void warp_bilinear_kernel(
    const float* __restrict__ img,
    const float* __restrict__ flo,
    float* __restrict__ out)
{
    __shared__ __half2 tile[TROWS * STRIDE];   // 33024 B

    const int bx = blockIdx.x;                 // 0 .. 511
    const int b  = bx >> 6;                    // 64 strips per batch
    const int h0 = (bx & 63) * TY;
    const int w  = threadIdx.x;                // one column per thread
    const int lane = w & 31;
    const int row_lo = h0 - HALO;

    // Fill mapping, analytic: slot_k = w + 512k -> row (w>>7)+4k, col (w&127)*4
    const int rbase = w >> 7;                  // 0..3
    const int fcol  = (w & 127) << 2;          // 0..508

    // ---- Per-pixel geometry (channel-invariant) ----
    int pk[TY];            // x0 | f2<<10 | dx<<20 | dy<<21 | fb<<22
    unsigned wq[TY];       // xw u16 | yw u16 << 16

    const int flo_b = (b * 2) * HW_;
    #pragma unroll
    for (int i = 0; i < TY; i++) {
        int h = h0 + i;
        float fx = __ldg(flo + flo_b + h * W_ + w);
        float fy = __ldg(flo + flo_b + HW_ + h * W_ + w);

        float px = (float)w + fx;
        float py = (float)h + fy;
        float x0f = floorf(px);
        float y0f = floorf(py);
        float xw = px - x0f;                   // weights from UNclamped floor
        float yw = py - y0f;
        wq[i] = __float2uint_rn(xw * 65535.0f)
              | (__float2uint_rn(yw * 65535.0f) << 16);

        int x0 = (int)fminf(fmaxf(x0f,        0.0f), (float)(W_ - 1));
        int x1 = (int)fminf(fmaxf(x0f + 1.0f, 0.0f), (float)(W_ - 1));
        int y0 = (int)fminf(fmaxf(y0f,        0.0f), (float)(H_ - 1));
        int y1 = (int)fminf(fmaxf(y0f + 1.0f, 0.0f), (float)(H_ - 1));

        int dx = x1 - x0;
        int dy = y1 - y0;
        int fb = (y0 < row_lo) || (y1 > row_lo + TROWS - 1);
        int f2 = fb ? y0 : (y0 - row_lo);
        pk[i] = x0 | (f2 << 10) | (dx << 20) | (dy << 21) | (fb ? FB_BIT : 0);
    }

    const float inv16 = 1.0f / 65535.0f;
    const float* bimg = img + (size_t)b * C_ * HW_;

    float4 v0, v1, v2, v3;                     // pipeline registers (16 regs)

    // LDG fill for channel ch into registers
    auto fill_regs = [&](int ch) {
        const float* plane = bimg + (size_t)ch * HW_;
        #pragma unroll
        for (int k = 0; k < 4; k++) {
            int gy = min(max(row_lo + rbase + 4 * k, 0), H_ - 1);
            float4 t = __ldg((const float4*)(plane + gy * W_ + fcol));
            if (k == 0) v0 = t; else if (k == 1) v1 = t;
            else if (k == 2) v2 = t; else v3 = t;
        }
    };

    // Convert registers -> fp16 pairs -> SMEM (ch: channel being published)
    auto convert_sts = [&](int ch) {
        const float* plane = bimg + (size_t)ch * HW_;
        #pragma unroll
        for (int k = 0; k < 4; k++) {
            float4 t = (k == 0) ? v0 : (k == 1) ? v1 : (k == 2) ? v2 : v3;
            float v4 = __shfl_down_sync(0xffffffffu, t.x, 1);
            if (fcol == 508) {
                v4 = t.w;                       // x=511 pair clamps
            } else if (lane == 31) {            // bridge to next slot's first col
                int gy = min(max(row_lo + rbase + 4 * k, 0), H_ - 1);
                v4 = __ldg(plane + gy * W_ + fcol + 4);
            }
            __half2 p0 = __floats2half2_rn(t.x, t.y);
            __half2 p1 = __floats2half2_rn(t.y, t.z);
            __half2 p2 = __floats2half2_rn(t.z, t.w);
            __half2 p3 = __floats2half2_rn(t.w, v4);
            uint4 pkt;
            pkt.x = *reinterpret_cast<unsigned*>(&p0);
            pkt.y = *reinterpret_cast<unsigned*>(&p1);
            pkt.z = *reinterpret_cast<unsigned*>(&p2);
            pkt.w = *reinterpret_cast<unsigned*>(&p3);
            *(uint4*)&tile[(rbase + 4 * k) * STRIDE + fcol] = pkt;
        }
    };

    fill_regs(0);
    convert_sts(0);
    __syncthreads();

    for (int c = 0; c < C_; c++) {
        if (c + 1 < C_) fill_regs(c + 1);      // LDG next channel; hides under gathers

        const float* plane  = bimg + (size_t)c * HW_;
        float*       oplane = out + ((size_t)(b * C_ + c)) * HW_;

        #pragma unroll
        for (int i = 0; i < TY; i++) {
            int p  = pk[i];
            int x0 = p & 1023;
            int f2 = (p >> 10) & 1023;
            int dx = (p >> 20) & 1;
            int dy = (p >> 21) & 1;

            float Ia, Ib, Ic, Id;
            if (!(p & FB_BIT)) {
                float2 t0 = __half22float2(tile[f2 * STRIDE + x0]);
                float2 t1 = __half22float2(tile[(f2 + dy) * STRIDE + x0]);
                Ia = t0.x;  Ic = dx ? t0.y : t0.x;
                Ib = t1.x;  Id = dx ? t1.y : t1.x;
            } else {                            // f2 = global y0
                const float* g  = plane + f2 * W_ + x0;
                const float* g1 = g + dy * W_;
                Ia = __ldg(g);  Ic = __ldg(g + dx);
                Ib = __ldg(g1); Id = __ldg(g1 + dx);
            }

            unsigned q = wq[i];
            float xw = (float)(q & 0xffffu) * inv16;
            float yw = (float)(q >> 16)     * inv16;
            float wa = (1.0f - xw) * (1.0f - yw);
            float wb = (1.0f - xw) * yw;
            float wc = xw * (1.0f - yw);
            float wd = xw * yw;

            float r = wa * Ia;
            r = fmaf(wb, Ib, r);
            r = fmaf(wc, Ic, r);
            r = fmaf(wd, Id, r);
            oplane[(h0 + i) * W_ + w] = r;
        }

        if (c + 1 < C_) {
            __syncthreads();                    // all reads of channel c done
            convert_sts(c + 1);                 // publish channel c+1
            __syncthreads();
        }
    }
}

extern "C" void kernel_launch(void* const* d_in, const int* in_sizes, int n_in,
                              void* d_out, int out_size)
{
    const float* img = (const float*)d_in[0];
    const float* flo = (const float*)d_in[1];
    float* out = (float*)d_out;

    const int blocks = B_ * (H_ / TY);   // 512
    warp_bilinear_kernel<<<blocks, THREADS>>>(img, flo, out);
}

// round 10
// speedup vs baseline: 3.5366x; 3.5366x over previous
#include <cuda_runtime.h>

// Bilinear flow warp, direct gathers, warp = 16x2 pixel patch.
//   img: [B=8, C=16, H=512, W=512] f32
//   flo: [B=8, 2,   H=512, W=512] f32
//   out: [B=8, C=16, H=512, W=512] f32
//
// Identical math to the R1 kernel (one thread per pixel, 16 channels
// unrolled, 4 scalar gather LDGs per channel). Only the thread->pixel map
// changes: each warp covers a 16-wide x 2-tall patch instead of 32x1, which
// shrinks the warp's gather sector footprint (x-span 16+jitter instead of
// 32+jitter) by ~45% at the same instruction count.

#define B_ 8
#define C_ 16
#define H_ 512
#define W_ 512
#define HW_ (H_ * W_)

__global__ __launch_bounds__(256) void warp_bilinear_kernel(
    const float* __restrict__ img,
    const float* __restrict__ flo,
    float* __restrict__ out)
{
    const int lane = threadIdx.x & 31;
    const int wid  = threadIdx.x >> 5;          // 0..7
    // warp patch: 16 wide x 2 tall; block tile: 32 wide x 8 tall
    const int lx = lane & 15;
    const int ly = lane >> 4;                   // 0..1
    const int wx = wid & 1;                     // 0..1
    const int wy = wid >> 1;                    // 0..3

    const int x = blockIdx.x * 32 + wx * 16 + lx;
    const int y = blockIdx.y * 8  + wy * 2  + ly;
    const int b = blockIdx.z;

    // flo layout [B,2,H,W]
    const int flo_base = ((b * 2) * H_ + y) * W_ + x;
    float fx = __ldg(flo + flo_base);
    float fy = __ldg(flo + flo_base + HW_);

    float px = (float)x + fx;
    float py = (float)y + fy;

    float x0f = floorf(px);
    float y0f = floorf(py);
    float xw  = px - x0f;        // weights from UNclamped floor (matches ref)
    float yw  = py - y0f;

    int x0 = (int)fminf(fmaxf(x0f,        0.0f), (float)(W_ - 1));
    int x1 = (int)fminf(fmaxf(x0f + 1.0f, 0.0f), (float)(W_ - 1));
    int y0 = (int)fminf(fmaxf(y0f,        0.0f), (float)(H_ - 1));
    int y1 = (int)fminf(fmaxf(y0f + 1.0f, 0.0f), (float)(H_ - 1));

    float wa = (1.0f - xw) * (1.0f - yw);
    float wb = (1.0f - xw) * yw;
    float wc = xw * (1.0f - yw);
    float wd = xw * yw;

    int o00 = y0 * W_ + x0;
    int o10 = y1 * W_ + x0;
    int o01 = y0 * W_ + x1;
    int o11 = y1 * W_ + x1;

    const float* ibase = img + (size_t)b * C_ * HW_;
    float*       obase = out + (size_t)b * C_ * HW_ + y * W_ + x;

    #pragma unroll
    for (int c = 0; c < C_; c++) {
        const float* p = ibase + c * HW_;
        float Ia = __ldg(p + o00);
        float Ib = __ldg(p + o10);
        float Ic = __ldg(p + o01);
        float Id = __ldg(p + o11);
        float r = wa * Ia;
        r = fmaf(wb, Ib, r);
        r = fmaf(wc, Ic, r);
        r = fmaf(wd, Id, r);
        obase[c * HW_] = r;
    }
}

extern "C" void kernel_launch(void* const* d_in, const int* in_sizes, int n_in,
                              void* d_out, int out_size)
{
    const float* img = (const float*)d_in[0];
    const float* flo = (const float*)d_in[1];
    float* out = (float*)d_out;

    dim3 grid(W_ / 32, H_ / 8, B_);   // (16, 64, 8) = 8192 blocks
    warp_bilinear_kernel<<<grid, 256>>>(img, flo, out);
}